// round 1
// baseline (speedup 1.0000x reference)
#include <cuda_runtime.h>
#include <cuda_bf16.h>
#include <mma.h>
#include <cstdint>

using namespace nvcuda;

// Problem dims
#define T_DIM 2048
#define B_DIM 16
#define D_DIM 1024
#define N3D   3072          // 3*D
#define MROWS (T_DIM * B_DIM)   // 32768
#define HALF  512
#define EPS   1e-5f

// Chunked scan config
#define NCHUNK 16
#define CHUNK  128          // T_DIM / NCHUNK

// ---------------- scratch (device globals; no allocations allowed) ------------
__device__ float g_pre[(size_t)MROWS * N3D];                 // ~402 MB
__device__ float g_cA [2 * NCHUNK * B_DIM * HALF];           // chunk A products
__device__ float g_cB [2 * NCHUNK * B_DIM * HALF];           // chunk B accums
__device__ float g_hin[2 * NCHUNK * B_DIM * HALF];           // chunk entry states

// =============================================================================
// Kernel 1: GEMM  pre[M=32768, N=3072] = input[M,1024] @ W[1024,3072]  (tf32)
// Block tile 128x128, BK=32, 8 warps (4x2), warp tile 32x64 (2x4 wmma 16x16x8)
// =============================================================================
#define BM 128
#define BN 128
#define BK 32
#define LDA_S 36    // BK + 4 pad (multiple of 4)
#define LDB_S 132   // BN + 4 pad (multiple of 4)

__global__ __launch_bounds__(256) void gemm_tf32_kernel(
    const float* __restrict__ Ag,   // [MROWS, 1024]
    const float* __restrict__ Wg)   // [1024, 3072]
{
    __shared__ float sA[BM][LDA_S];
    __shared__ float sB[BK][LDB_S];

    const int tid = threadIdx.x;
    const int bm = blockIdx.y * BM;
    const int bn = blockIdx.x * BN;

    const int warp = tid >> 5;
    const int wm = warp & 3;        // 0..3 -> rows wm*32
    const int wn = warp >> 2;       // 0..1 -> cols wn*64

    wmma::fragment<wmma::accumulator, 16, 16, 8, float> acc[2][4];
#pragma unroll
    for (int mi = 0; mi < 2; mi++)
#pragma unroll
        for (int ni = 0; ni < 4; ni++)
            wmma::fill_fragment(acc[mi][ni], 0.0f);

    for (int k0 = 0; k0 < D_DIM; k0 += BK) {
        // Load A tile: 128x32 floats = 1024 float4
#pragma unroll
        for (int l = 0; l < 4; l++) {
            int e = tid + l * 256;
            int r = e >> 3;
            int c4 = (e & 7) * 4;
            float4 v = *(const float4*)(Ag + (size_t)(bm + r) * D_DIM + k0 + c4);
            *(float4*)&sA[r][c4] = v;
        }
        // Load B tile: 32x128 floats = 1024 float4
#pragma unroll
        for (int l = 0; l < 4; l++) {
            int e = tid + l * 256;
            int r = e >> 5;
            int c4 = (e & 31) * 4;
            float4 v = *(const float4*)(Wg + (size_t)(k0 + r) * N3D + bn + c4);
            *(float4*)&sB[r][c4] = v;
        }
        __syncthreads();

#pragma unroll
        for (int kk = 0; kk < BK / 8; kk++) {
            wmma::fragment<wmma::matrix_a, 16, 16, 8, wmma::precision::tf32, wmma::row_major> af[2];
            wmma::fragment<wmma::matrix_b, 16, 16, 8, wmma::precision::tf32, wmma::row_major> bf[4];
#pragma unroll
            for (int mi = 0; mi < 2; mi++) {
                wmma::load_matrix_sync(af[mi], &sA[wm * 32 + mi * 16][kk * 8], LDA_S);
#pragma unroll
                for (int i = 0; i < af[mi].num_elements; i++)
                    af[mi].x[i] = wmma::__float_to_tf32(af[mi].x[i]);
            }
#pragma unroll
            for (int ni = 0; ni < 4; ni++) {
                wmma::load_matrix_sync(bf[ni], &sB[kk * 8][wn * 64 + ni * 16], LDB_S);
#pragma unroll
                for (int i = 0; i < bf[ni].num_elements; i++)
                    bf[ni].x[i] = wmma::__float_to_tf32(bf[ni].x[i]);
            }
#pragma unroll
            for (int mi = 0; mi < 2; mi++)
#pragma unroll
                for (int ni = 0; ni < 4; ni++)
                    wmma::mma_sync(acc[mi][ni], af[mi], bf[ni], acc[mi][ni]);
        }
        __syncthreads();
    }

    // Epilogue: store to g_pre
#pragma unroll
    for (int mi = 0; mi < 2; mi++)
#pragma unroll
        for (int ni = 0; ni < 4; ni++) {
            float* dst = g_pre + (size_t)(bm + wm * 32 + mi * 16) * N3D + bn + wn * 64 + ni * 16;
            wmma::store_matrix_sync(dst, acc[mi][ni], N3D, wmma::mem_row_major);
        }
}

// =============================================================================
// Kernel 2: LayerNorm over 3072 + gamma/beta + sigmoid on gate segments.
// One block (256 threads) per row. In-place on g_pre.
// Layout per row: [g(1024) | x(1024) | hg(1024)]; sigmoid applied to g and hg.
// =============================================================================
__global__ __launch_bounds__(256) void ln_kernel(
    const float* __restrict__ gamma, const float* __restrict__ beta)
{
    const int row = blockIdx.x;
    const int tid = threadIdx.x;
    float* p = g_pre + (size_t)row * N3D;

    float v[12];
    float s = 0.f, s2 = 0.f;
#pragma unroll
    for (int i = 0; i < 12; i++) {
        float x = p[tid + i * 256];
        v[i] = x;
        s += x;
        s2 += x * x;
    }
    // warp reduce
#pragma unroll
    for (int o = 16; o; o >>= 1) {
        s  += __shfl_xor_sync(0xffffffffu, s, o);
        s2 += __shfl_xor_sync(0xffffffffu, s2, o);
    }
    __shared__ float shs[8], shs2[8];
    __shared__ float s_mu, s_rsig;
    const int lane = tid & 31, wid = tid >> 5;
    if (lane == 0) { shs[wid] = s; shs2[wid] = s2; }
    __syncthreads();
    if (tid == 0) {
        float a = 0.f, b = 0.f;
#pragma unroll
        for (int i = 0; i < 8; i++) { a += shs[i]; b += shs2[i]; }
        float mu = a * (1.0f / N3D);
        float var = b * (1.0f / N3D) - mu * mu;
        s_mu = mu;
        s_rsig = rsqrtf(var + EPS);
    }
    __syncthreads();
    const float mu = s_mu, rsig = s_rsig;

#pragma unroll
    for (int i = 0; i < 12; i++) {
        int j = tid + i * 256;
        float y = (v[i] - mu) * rsig * gamma[j] + beta[j];
        if (j < D_DIM || j >= 2 * D_DIM)       // g and h_gate segments -> sigmoid
            y = 1.0f / (1.0f + __expf(-y));
        p[j] = y;
    }
}

// =============================================================================
// Chunked linear recurrence. h[t] = (1-g[t])*h[prev] + g[t]*x[t]
// dir 0: forward over t (channels [0,512));  dir 1: reverse (channels [512,1024)).
// =============================================================================
__device__ __forceinline__ void decode_idx(int idx, int& c, int& b, int& chunk, int& dir) {
    c = idx & (HALF - 1);
    b = (idx >> 9) & (B_DIM - 1);
    chunk = (idx >> 13) & (NCHUNK - 1);
    dir = idx >> 17;
}

// Pass A: per-chunk affine composition (A = prod a, B = accumulated b)
__global__ __launch_bounds__(256) void scan_passA_kernel()
{
    int idx = blockIdx.x * 256 + threadIdx.x;
    int c, b, chunk, dir;
    decode_idx(idx, c, b, chunk, dir);

    const int colg = dir ? (HALF + c) : c;
    const int colx = D_DIM + colg;
    const int t0 = chunk * CHUNK;

    float A = 1.f, Bv = 0.f;
    if (dir == 0) {
        for (int i = 0; i < CHUNK; i++) {
            int t = t0 + i;
            size_t base = (size_t)(t * B_DIM + b) * N3D;
            float g = g_pre[base + colg];
            float x = g_pre[base + colx];
            float a = 1.f - g;
            Bv = a * Bv + g * x;
            A *= a;
        }
    } else {
        for (int i = CHUNK - 1; i >= 0; i--) {
            int t = t0 + i;
            size_t base = (size_t)(t * B_DIM + b) * N3D;
            float g = g_pre[base + colg];
            float x = g_pre[base + colx];
            float a = 1.f - g;
            Bv = a * Bv + g * x;
            A *= a;
        }
    }
    int off = ((dir * NCHUNK + chunk) * B_DIM + b) * HALF + c;
    g_cA[off] = A;
    g_cB[off] = Bv;
}

// Pass B: tiny prefix across 16 chunks per sequence
__global__ __launch_bounds__(256) void scan_passB_kernel()
{
    int idx = blockIdx.x * 256 + threadIdx.x;   // 2*16*512 = 16384 threads
    int c = idx & (HALF - 1);
    int b = (idx >> 9) & (B_DIM - 1);
    int dir = idx >> 13;

    float h = 0.f;
    if (dir == 0) {
        for (int k = 0; k < NCHUNK; k++) {
            int off = ((0 * NCHUNK + k) * B_DIM + b) * HALF + c;
            g_hin[off] = h;
            h = g_cA[off] * h + g_cB[off];
        }
    } else {
        for (int k = NCHUNK - 1; k >= 0; k--) {
            int off = ((1 * NCHUNK + k) * B_DIM + b) * HALF + c;
            g_hin[off] = h;
            h = g_cA[off] * h + g_cB[off];
        }
    }
}

// Pass C: replay chunk with correct initial state; fuse final output blend.
// out[t,b,ch] = (1 - hg)*h + input*hg
__global__ __launch_bounds__(256) void scan_passC_kernel(
    const float* __restrict__ inp, float* __restrict__ out)
{
    int idx = blockIdx.x * 256 + threadIdx.x;
    int c, b, chunk, dir;
    decode_idx(idx, c, b, chunk, dir);

    const int colg = dir ? (HALF + c) : c;
    const int colx = D_DIM + colg;
    const int colh = 2 * D_DIM + colg;
    const int t0 = chunk * CHUNK;

    float h = g_hin[((dir * NCHUNK + chunk) * B_DIM + b) * HALF + c];

    if (dir == 0) {
        for (int i = 0; i < CHUNK; i++) {
            int t = t0 + i;
            size_t base = (size_t)(t * B_DIM + b) * N3D;
            float g = g_pre[base + colg];
            float x = g_pre[base + colx];
            h = (1.f - g) * h + g * x;
            float hg = g_pre[base + colh];
            size_t ib = (size_t)(t * B_DIM + b) * D_DIM + colg;
            out[ib] = h + hg * (inp[ib] - h);
        }
    } else {
        for (int i = CHUNK - 1; i >= 0; i--) {
            int t = t0 + i;
            size_t base = (size_t)(t * B_DIM + b) * N3D;
            float g = g_pre[base + colg];
            float x = g_pre[base + colx];
            h = (1.f - g) * h + g * x;
            float hg = g_pre[base + colh];
            size_t ib = (size_t)(t * B_DIM + b) * D_DIM + colg;
            out[ib] = h + hg * (inp[ib] - h);
        }
    }
}

// =============================================================================
extern "C" void kernel_launch(void* const* d_in, const int* in_sizes, int n_in,
                              void* d_out, int out_size)
{
    const float* inp   = (const float*)d_in[0];   // (T,B,D)
    const float* W     = (const float*)d_in[1];   // (D, 3D)
    const float* gamma = (const float*)d_in[2];   // (3D,)
    const float* beta  = (const float*)d_in[3];   // (3D,)
    float* out = (float*)d_out;

    dim3 ggrid(N3D / BN, MROWS / BM);             // 24 x 256
    gemm_tf32_kernel<<<ggrid, 256>>>(inp, W);

    ln_kernel<<<MROWS, 256>>>(gamma, beta);

    scan_passA_kernel<<<(2 * NCHUNK * B_DIM * HALF) / 256, 256>>>();
    scan_passB_kernel<<<(2 * B_DIM * HALF) / 256, 256>>>();
    scan_passC_kernel<<<(2 * NCHUNK * B_DIM * HALF) / 256, 256>>>(inp, out);
}

// round 3
// speedup vs baseline: 1.1733x; 1.1733x over previous
#include <cuda_runtime.h>
#include <cuda_bf16.h>
#include <cuda_pipeline.h>
#include <mma.h>
#include <cstdint>

using namespace nvcuda;

// Problem dims
#define T_DIM 2048
#define B_DIM 16
#define D_DIM 1024
#define N3D   3072          // 3*D
#define MROWS (T_DIM * B_DIM)   // 32768
#define HALF  512
#define EPS   1e-5f

// Chunked scan config
#define NCHUNK 16
#define CHUNK  128          // T_DIM / NCHUNK

// ---------------- scratch (device globals; no allocations allowed) ------------
__device__ float g_pre[(size_t)MROWS * N3D];                 // ~402 MB
__device__ float g_cA [2 * NCHUNK * B_DIM * HALF];           // chunk A products
__device__ float g_cB [2 * NCHUNK * B_DIM * HALF];           // chunk B accums
__device__ float g_hin[2 * NCHUNK * B_DIM * HALF];           // chunk entry states

// =============================================================================
// Kernel 1: GEMM  pre[M=32768, N=3072] = input[M,1024] @ W[1024,3072]  (tf32)
// 128x128x32 tiles, 3-stage cp.async pipeline, 8 warps, warp tile 32x64.
// =============================================================================
#define BM 128
#define BN 128
#define BK 32
#define KTILES (D_DIM / BK)     // 32
#define STAGES 3
#define LDA_S 36    // BK + 4 pad (row = 144B, 16B aligned)
#define LDB_S 132   // BN + 4 pad (row = 528B, 16B aligned)
#define SA_STAGE (BM * LDA_S)   // 4608 floats
#define SB_STAGE (BK * LDB_S)   // 4224 floats
#define SMEM_FLOATS (STAGES * (SA_STAGE + SB_STAGE))
#define SMEM_BYTES  (SMEM_FLOATS * 4)   // 105,984 B

__device__ __forceinline__ void load_tile_async(
    float* sA, float* sB,
    const float* __restrict__ Ag, const float* __restrict__ Wg,
    int bm, int bn, int k0, int tid)
{
    // A tile: 128 rows x 32 floats = 1024 x 16B ops, 4 per thread
#pragma unroll
    for (int l = 0; l < 4; l++) {
        int e = tid + l * 256;
        int r = e >> 3;
        int c4 = (e & 7) * 4;
        __pipeline_memcpy_async(sA + r * LDA_S + c4,
                                Ag + (size_t)(bm + r) * D_DIM + k0 + c4, 16);
    }
    // B tile: 32 rows x 128 floats = 1024 x 16B ops, 4 per thread
#pragma unroll
    for (int l = 0; l < 4; l++) {
        int e = tid + l * 256;
        int r = e >> 5;
        int c4 = (e & 31) * 4;
        __pipeline_memcpy_async(sB + r * LDB_S + c4,
                                Wg + (size_t)(k0 + r) * N3D + bn + c4, 16);
    }
}

__global__ __launch_bounds__(256, 2) void gemm_tf32_kernel(
    const float* __restrict__ Ag,   // [MROWS, 1024]
    const float* __restrict__ Wg)   // [1024, 3072]
{
    extern __shared__ float smem[];
    float* sAbase = smem;                          // STAGES * SA_STAGE
    float* sBbase = smem + STAGES * SA_STAGE;      // STAGES * SB_STAGE

    const int tid = threadIdx.x;
    const int bm = blockIdx.y * BM;
    const int bn = blockIdx.x * BN;

    const int warp = tid >> 5;
    const int wm = warp & 3;        // 0..3 -> rows wm*32
    const int wn = warp >> 2;       // 0..1 -> cols wn*64

    wmma::fragment<wmma::accumulator, 16, 16, 8, float> acc[2][4];
#pragma unroll
    for (int mi = 0; mi < 2; mi++)
#pragma unroll
        for (int ni = 0; ni < 4; ni++)
            wmma::fill_fragment(acc[mi][ni], 0.0f);

    // Prologue: preload stages 0, 1
#pragma unroll
    for (int s = 0; s < STAGES - 1; s++) {
        load_tile_async(sAbase + s * SA_STAGE, sBbase + s * SB_STAGE,
                        Ag, Wg, bm, bn, s * BK, tid);
        __pipeline_commit();
    }

    for (int kt = 0; kt < KTILES; kt++) {
        __pipeline_wait_prior(STAGES - 2);
        __syncthreads();

        // Prefetch kt+2 into buffer (kt+2)%3 (== buffer computed at kt-1)
        int kn = kt + STAGES - 1;
        if (kn < KTILES) {
            int sw = kn % STAGES;
            load_tile_async(sAbase + sw * SA_STAGE, sBbase + sw * SB_STAGE,
                            Ag, Wg, bm, bn, kn * BK, tid);
        }
        __pipeline_commit();

        const float* sA = sAbase + (kt % STAGES) * SA_STAGE;
        const float* sB = sBbase + (kt % STAGES) * SB_STAGE;

#pragma unroll
        for (int kk = 0; kk < BK / 8; kk++) {
            wmma::fragment<wmma::matrix_a, 16, 16, 8, wmma::precision::tf32, wmma::row_major> af[2];
            wmma::fragment<wmma::matrix_b, 16, 16, 8, wmma::precision::tf32, wmma::row_major> bf[4];
#pragma unroll
            for (int mi = 0; mi < 2; mi++) {
                wmma::load_matrix_sync(af[mi], sA + (wm * 32 + mi * 16) * LDA_S + kk * 8, LDA_S);
#pragma unroll
                for (int i = 0; i < af[mi].num_elements; i++)
                    af[mi].x[i] = wmma::__float_to_tf32(af[mi].x[i]);
            }
#pragma unroll
            for (int ni = 0; ni < 4; ni++) {
                wmma::load_matrix_sync(bf[ni], sB + (kk * 8) * LDB_S + wn * 64 + ni * 16, LDB_S);
#pragma unroll
                for (int i = 0; i < bf[ni].num_elements; i++)
                    bf[ni].x[i] = wmma::__float_to_tf32(bf[ni].x[i]);
            }
#pragma unroll
            for (int mi = 0; mi < 2; mi++)
#pragma unroll
                for (int ni = 0; ni < 4; ni++)
                    wmma::mma_sync(acc[mi][ni], af[mi], bf[ni], acc[mi][ni]);
        }
    }

    // Epilogue: store to g_pre
#pragma unroll
    for (int mi = 0; mi < 2; mi++)
#pragma unroll
        for (int ni = 0; ni < 4; ni++) {
            float* dst = g_pre + (size_t)(bm + wm * 32 + mi * 16) * N3D + bn + wn * 64 + ni * 16;
            wmma::store_matrix_sync(dst, acc[mi][ni], N3D, wmma::mem_row_major);
        }
}

// =============================================================================
// Kernel 2: LayerNorm over 3072 + gamma/beta + sigmoid on gate segments.
// One block (256 threads) per row. In-place on g_pre.
// =============================================================================
__global__ __launch_bounds__(256) void ln_kernel(
    const float* __restrict__ gamma, const float* __restrict__ beta)
{
    const int row = blockIdx.x;
    const int tid = threadIdx.x;
    float* p = g_pre + (size_t)row * N3D;

    float v[12];
    float s = 0.f, s2 = 0.f;
#pragma unroll
    for (int i = 0; i < 12; i++) {
        float x = p[tid + i * 256];
        v[i] = x;
        s += x;
        s2 += x * x;
    }
#pragma unroll
    for (int o = 16; o; o >>= 1) {
        s  += __shfl_xor_sync(0xffffffffu, s, o);
        s2 += __shfl_xor_sync(0xffffffffu, s2, o);
    }
    __shared__ float shs[8], shs2[8];
    __shared__ float s_mu, s_rsig;
    const int lane = tid & 31, wid = tid >> 5;
    if (lane == 0) { shs[wid] = s; shs2[wid] = s2; }
    __syncthreads();
    if (tid == 0) {
        float a = 0.f, b = 0.f;
#pragma unroll
        for (int i = 0; i < 8; i++) { a += shs[i]; b += shs2[i]; }
        float mu = a * (1.0f / N3D);
        float var = b * (1.0f / N3D) - mu * mu;
        s_mu = mu;
        s_rsig = rsqrtf(var + EPS);
    }
    __syncthreads();
    const float mu = s_mu, rsig = s_rsig;

#pragma unroll
    for (int i = 0; i < 12; i++) {
        int j = tid + i * 256;
        float y = (v[i] - mu) * rsig * gamma[j] + beta[j];
        if (j < D_DIM || j >= 2 * D_DIM)       // g and h_gate segments -> sigmoid
            y = 1.0f / (1.0f + __expf(-y));
        p[j] = y;
    }
}

// =============================================================================
// Chunked linear recurrence. h[t] = (1-g[t])*h[prev] + g[t]*x[t]
// =============================================================================
__device__ __forceinline__ void decode_idx(int idx, int& c, int& b, int& chunk, int& dir) {
    c = idx & (HALF - 1);
    b = (idx >> 9) & (B_DIM - 1);
    chunk = (idx >> 13) & (NCHUNK - 1);
    dir = idx >> 17;
}

__global__ __launch_bounds__(256) void scan_passA_kernel()
{
    int idx = blockIdx.x * 256 + threadIdx.x;
    int c, b, chunk, dir;
    decode_idx(idx, c, b, chunk, dir);

    const int colg = dir ? (HALF + c) : c;
    const int colx = D_DIM + colg;
    const int t0 = chunk * CHUNK;

    float A = 1.f, Bv = 0.f;
    if (dir == 0) {
        for (int i = 0; i < CHUNK; i++) {
            int t = t0 + i;
            size_t base = (size_t)(t * B_DIM + b) * N3D;
            float g = g_pre[base + colg];
            float x = g_pre[base + colx];
            float a = 1.f - g;
            Bv = a * Bv + g * x;
            A *= a;
        }
    } else {
        for (int i = CHUNK - 1; i >= 0; i--) {
            int t = t0 + i;
            size_t base = (size_t)(t * B_DIM + b) * N3D;
            float g = g_pre[base + colg];
            float x = g_pre[base + colx];
            float a = 1.f - g;
            Bv = a * Bv + g * x;
            A *= a;
        }
    }
    int off = ((dir * NCHUNK + chunk) * B_DIM + b) * HALF + c;
    g_cA[off] = A;
    g_cB[off] = Bv;
}

__global__ __launch_bounds__(256) void scan_passB_kernel()
{
    int idx = blockIdx.x * 256 + threadIdx.x;   // 2*16*512 = 16384 threads
    int c = idx & (HALF - 1);
    int b = (idx >> 9) & (B_DIM - 1);
    int dir = idx >> 13;

    float h = 0.f;
    if (dir == 0) {
        for (int k = 0; k < NCHUNK; k++) {
            int off = ((0 * NCHUNK + k) * B_DIM + b) * HALF + c;
            g_hin[off] = h;
            h = g_cA[off] * h + g_cB[off];
        }
    } else {
        for (int k = NCHUNK - 1; k >= 0; k--) {
            int off = ((1 * NCHUNK + k) * B_DIM + b) * HALF + c;
            g_hin[off] = h;
            h = g_cA[off] * h + g_cB[off];
        }
    }
}

__global__ __launch_bounds__(256) void scan_passC_kernel(
    const float* __restrict__ inp, float* __restrict__ out)
{
    int idx = blockIdx.x * 256 + threadIdx.x;
    int c, b, chunk, dir;
    decode_idx(idx, c, b, chunk, dir);

    const int colg = dir ? (HALF + c) : c;
    const int colx = D_DIM + colg;
    const int colh = 2 * D_DIM + colg;
    const int t0 = chunk * CHUNK;

    float h = g_hin[((dir * NCHUNK + chunk) * B_DIM + b) * HALF + c];

    if (dir == 0) {
        for (int i = 0; i < CHUNK; i++) {
            int t = t0 + i;
            size_t base = (size_t)(t * B_DIM + b) * N3D;
            float g = g_pre[base + colg];
            float x = g_pre[base + colx];
            h = (1.f - g) * h + g * x;
            float hg = g_pre[base + colh];
            size_t ib = (size_t)(t * B_DIM + b) * D_DIM + colg;
            out[ib] = h + hg * (inp[ib] - h);
        }
    } else {
        for (int i = CHUNK - 1; i >= 0; i--) {
            int t = t0 + i;
            size_t base = (size_t)(t * B_DIM + b) * N3D;
            float g = g_pre[base + colg];
            float x = g_pre[base + colx];
            h = (1.f - g) * h + g * x;
            float hg = g_pre[base + colh];
            size_t ib = (size_t)(t * B_DIM + b) * D_DIM + colg;
            out[ib] = h + hg * (inp[ib] - h);
        }
    }
}

// =============================================================================
extern "C" void kernel_launch(void* const* d_in, const int* in_sizes, int n_in,
                              void* d_out, int out_size)
{
    const float* inp   = (const float*)d_in[0];   // (T,B,D)
    const float* W     = (const float*)d_in[1];   // (D, 3D)
    const float* gamma = (const float*)d_in[2];   // (3D,)
    const float* beta  = (const float*)d_in[3];   // (3D,)
    float* out = (float*)d_out;

    static bool attr_set = false;
    if (!attr_set) {
        cudaFuncSetAttribute(gemm_tf32_kernel,
                             cudaFuncAttributeMaxDynamicSharedMemorySize, SMEM_BYTES);
        attr_set = true;
    }

    dim3 ggrid(N3D / BN, MROWS / BM);             // 24 x 256
    gemm_tf32_kernel<<<ggrid, 256, SMEM_BYTES>>>(inp, W);

    ln_kernel<<<MROWS, 256>>>(gamma, beta);

    scan_passA_kernel<<<(2 * NCHUNK * B_DIM * HALF) / 256, 256>>>();
    scan_passB_kernel<<<(2 * B_DIM * HALF) / 256, 256>>>();
    scan_passC_kernel<<<(2 * NCHUNK * B_DIM * HALF) / 256, 256>>>(inp, out);
}

// round 6
// speedup vs baseline: 2.4442x; 2.0831x over previous
#include <cuda_runtime.h>
#include <cuda_bf16.h>
#include <cuda_pipeline.h>
#include <cstdint>

// Problem dims
#define T_DIM 2048
#define B_DIM 16
#define D_DIM 1024
#define N3D   3072          // 3*D
#define MROWS (T_DIM * B_DIM)   // 32768
#define HALF  512
#define EPS   1e-5f

// Chunked scan config
#define NCHUNK 16
#define CHUNK  128          // T_DIM / NCHUNK

// ---------------- scratch (device globals; no allocations allowed) ------------
__device__ float g_pre[(size_t)MROWS * N3D];                 // ~402 MB
__device__ float g_cA [2 * NCHUNK * B_DIM * HALF];
__device__ float g_cB [2 * NCHUNK * B_DIM * HALF];
__device__ float g_hin[2 * NCHUNK * B_DIM * HALF];

// =============================================================================
// Kernel 1: GEMM  pre[M=32768, N=3072] = input[M,1024] @ W[1024,3072]
// tf32 mma.sync m16n8k8, 128x128x32 tiles, 3-stage cp.async, 8 warps,
// warp tile 32x64 (2 m-atoms x 8 n-atoms). No conversion ops (HW truncation).
// =============================================================================
#define BM 128
#define BN 128
#define BK 32
#define KTILES (D_DIM / BK)     // 32
#define STAGES 3
#define LDA_S 36    // bank(addr) = (36*g + tg) % 32 = 4g+tg : conflict-free
#define LDB_S 136   // bank = (136*tg + g) % 32 = 8tg+g    : conflict-free
#define SA_STAGE (BM * LDA_S)   // 4608 floats
#define SB_STAGE (BK * LDB_S)   // 4352 floats
#define SMEM_FLOATS (STAGES * (SA_STAGE + SB_STAGE))
#define SMEM_BYTES  (SMEM_FLOATS * 4)   // 107,520 B

__device__ __forceinline__ void mma_tf32(float* c, const uint32_t* a, const uint32_t* b)
{
    asm volatile(
        "mma.sync.aligned.m16n8k8.row.col.f32.tf32.tf32.f32 "
        "{%0,%1,%2,%3}, {%4,%5,%6,%7}, {%8,%9}, {%0,%1,%2,%3};\n"
        : "+f"(c[0]), "+f"(c[1]), "+f"(c[2]), "+f"(c[3])
        : "r"(a[0]), "r"(a[1]), "r"(a[2]), "r"(a[3]), "r"(b[0]), "r"(b[1]));
}

__device__ __forceinline__ void load_tile_async(
    float* sA, float* sB,
    const float* __restrict__ Ag, const float* __restrict__ Wg,
    int bm, int bn, int k0, int tid)
{
    // A tile: 128 rows x 32 floats = 1024 x 16B ops, 4 per thread
#pragma unroll
    for (int l = 0; l < 4; l++) {
        int e = tid + l * 256;
        int r = e >> 3;
        int c4 = (e & 7) * 4;
        __pipeline_memcpy_async(sA + r * LDA_S + c4,
                                Ag + (size_t)(bm + r) * D_DIM + k0 + c4, 16);
    }
    // B tile: 32 rows x 128 floats = 1024 x 16B ops, 4 per thread
#pragma unroll
    for (int l = 0; l < 4; l++) {
        int e = tid + l * 256;
        int r = e >> 5;
        int c4 = (e & 31) * 4;
        __pipeline_memcpy_async(sB + r * LDB_S + c4,
                                Wg + (size_t)(k0 + r) * N3D + bn + c4, 16);
    }
}

__global__ __launch_bounds__(256, 2) void gemm_tf32_kernel(
    const float* __restrict__ Ag,   // [MROWS, 1024]
    const float* __restrict__ Wg)   // [1024, 3072]
{
    extern __shared__ float smem[];
    float* sAbase = smem;
    float* sBbase = smem + STAGES * SA_STAGE;

    const int tid = threadIdx.x;
    const int bm = blockIdx.y * BM;
    const int bn = blockIdx.x * BN;

    const int warp = tid >> 5;
    const int lane = tid & 31;
    const int wm = warp & 3;        // m offset wm*32
    const int wn = warp >> 2;       // n offset wn*64
    const int g  = lane >> 2;       // group id 0..7
    const int tg = lane & 3;        // thread-in-group 0..3

    float acc[2][8][4];
#pragma unroll
    for (int mi = 0; mi < 2; mi++)
#pragma unroll
        for (int ni = 0; ni < 8; ni++)
#pragma unroll
            for (int i = 0; i < 4; i++)
                acc[mi][ni][i] = 0.0f;

    // Prologue: preload stages 0, 1
#pragma unroll
    for (int s = 0; s < STAGES - 1; s++) {
        load_tile_async(sAbase + s * SA_STAGE, sBbase + s * SB_STAGE,
                        Ag, Wg, bm, bn, s * BK, tid);
        __pipeline_commit();
    }

    for (int kt = 0; kt < KTILES; kt++) {
        __pipeline_wait_prior(STAGES - 2);
        __syncthreads();

        int kn = kt + STAGES - 1;
        if (kn < KTILES) {
            int sw = kn % STAGES;
            load_tile_async(sAbase + sw * SA_STAGE, sBbase + sw * SB_STAGE,
                            Ag, Wg, bm, bn, kn * BK, tid);
        }
        __pipeline_commit();

        const float* sA = sAbase + (kt % STAGES) * SA_STAGE;
        const float* sB = sBbase + (kt % STAGES) * SB_STAGE;

        // Per-thread base pointers
        const float* a0p = sA + (wm * 32 + g) * LDA_S + tg;        // rows g / g+8 (+8*LDA_S), +16 for mi=1
        const float* b0p = sB + tg * LDB_S + wn * 64 + g;          // k rows tg / tg+4

#pragma unroll
        for (int kk = 0; kk < 4; kk++) {
            const int ko = kk * 8;
            uint32_t af[2][4];
#pragma unroll
            for (int mi = 0; mi < 2; mi++) {
                const float* ap = a0p + mi * 16 * LDA_S + ko;
                af[mi][0] = __float_as_uint(ap[0]);
                af[mi][1] = __float_as_uint(ap[8 * LDA_S]);
                af[mi][2] = __float_as_uint(ap[4]);
                af[mi][3] = __float_as_uint(ap[8 * LDA_S + 4]);
            }
            uint32_t bf[8][2];
#pragma unroll
            for (int ni = 0; ni < 8; ni++) {
                const float* bp = b0p + ko * LDB_S + ni * 8;
                bf[ni][0] = __float_as_uint(bp[0]);
                bf[ni][1] = __float_as_uint(bp[4 * LDB_S]);
            }
#pragma unroll
            for (int mi = 0; mi < 2; mi++)
#pragma unroll
                for (int ni = 0; ni < 8; ni++)
                    mma_tf32(acc[mi][ni], af[mi], bf[ni]);
        }
    }

    // Epilogue: store accumulators to g_pre.
    // Thread (g,tg) holds C[g][2tg], C[g][2tg+1], C[g+8][2tg], C[g+8][2tg+1]
#pragma unroll
    for (int mi = 0; mi < 2; mi++) {
        const int r0 = bm + wm * 32 + mi * 16 + g;
#pragma unroll
        for (int ni = 0; ni < 8; ni++) {
            const int col = bn + wn * 64 + ni * 8 + 2 * tg;
            float* p0 = g_pre + (size_t)r0 * N3D + col;
            *(float2*)p0 = make_float2(acc[mi][ni][0], acc[mi][ni][1]);
            float* p1 = g_pre + (size_t)(r0 + 8) * N3D + col;
            *(float2*)p1 = make_float2(acc[mi][ni][2], acc[mi][ni][3]);
        }
    }
}

// =============================================================================
// Kernel 2: LayerNorm over 3072 + gamma/beta + sigmoid on gate segments.
// =============================================================================
__global__ __launch_bounds__(256) void ln_kernel(
    const float* __restrict__ gamma, const float* __restrict__ beta)
{
    const int row = blockIdx.x;
    const int tid = threadIdx.x;
    float* p = g_pre + (size_t)row * N3D;

    float v[12];
    float s = 0.f, s2 = 0.f;
#pragma unroll
    for (int i = 0; i < 12; i++) {
        float x = p[tid + i * 256];
        v[i] = x;
        s += x;
        s2 += x * x;
    }
#pragma unroll
    for (int o = 16; o; o >>= 1) {
        s  += __shfl_xor_sync(0xffffffffu, s, o);
        s2 += __shfl_xor_sync(0xffffffffu, s2, o);
    }
    __shared__ float shs[8], shs2[8];
    __shared__ float s_mu, s_rsig;
    const int lane = tid & 31, wd = tid >> 5;
    if (lane == 0) { shs[wd] = s; shs2[wd] = s2; }
    __syncthreads();
    if (tid == 0) {
        float a = 0.f, b = 0.f;
#pragma unroll
        for (int i = 0; i < 8; i++) { a += shs[i]; b += shs2[i]; }
        float mu = a * (1.0f / N3D);
        float var = b * (1.0f / N3D) - mu * mu;
        s_mu = mu;
        s_rsig = rsqrtf(var + EPS);
    }
    __syncthreads();
    const float mu = s_mu, rsig = s_rsig;

#pragma unroll
    for (int i = 0; i < 12; i++) {
        int j = tid + i * 256;
        float y = (v[i] - mu) * rsig * gamma[j] + beta[j];
        if (j < D_DIM || j >= 2 * D_DIM)
            y = 1.0f / (1.0f + __expf(-y));
        p[j] = y;
    }
}

// =============================================================================
// Chunked linear recurrence.
// =============================================================================
__device__ __forceinline__ void decode_idx(int idx, int& c, int& b, int& chunk, int& dir) {
    c = idx & (HALF - 1);
    b = (idx >> 9) & (B_DIM - 1);
    chunk = (idx >> 13) & (NCHUNK - 1);
    dir = idx >> 17;
}

__global__ __launch_bounds__(256) void scan_passA_kernel()
{
    int idx = blockIdx.x * 256 + threadIdx.x;
    int c, b, chunk, dir;
    decode_idx(idx, c, b, chunk, dir);

    const int colg = dir ? (HALF + c) : c;
    const int colx = D_DIM + colg;
    const int t0 = chunk * CHUNK;

    float A = 1.f, Bv = 0.f;
    if (dir == 0) {
        for (int i = 0; i < CHUNK; i++) {
            size_t base = (size_t)((t0 + i) * B_DIM + b) * N3D;
            float g = g_pre[base + colg];
            float x = g_pre[base + colx];
            float a = 1.f - g;
            Bv = a * Bv + g * x;
            A *= a;
        }
    } else {
        for (int i = CHUNK - 1; i >= 0; i--) {
            size_t base = (size_t)((t0 + i) * B_DIM + b) * N3D;
            float g = g_pre[base + colg];
            float x = g_pre[base + colx];
            float a = 1.f - g;
            Bv = a * Bv + g * x;
            A *= a;
        }
    }
    int off = ((dir * NCHUNK + chunk) * B_DIM + b) * HALF + c;
    g_cA[off] = A;
    g_cB[off] = Bv;
}

__global__ __launch_bounds__(256) void scan_passB_kernel()
{
    int idx = blockIdx.x * 256 + threadIdx.x;
    int c = idx & (HALF - 1);
    int b = (idx >> 9) & (B_DIM - 1);
    int dir = idx >> 13;

    float h = 0.f;
    if (dir == 0) {
        for (int k = 0; k < NCHUNK; k++) {
            int off = ((0 * NCHUNK + k) * B_DIM + b) * HALF + c;
            g_hin[off] = h;
            h = g_cA[off] * h + g_cB[off];
        }
    } else {
        for (int k = NCHUNK - 1; k >= 0; k--) {
            int off = ((1 * NCHUNK + k) * B_DIM + b) * HALF + c;
            g_hin[off] = h;
            h = g_cA[off] * h + g_cB[off];
        }
    }
}

__global__ __launch_bounds__(256) void scan_passC_kernel(
    const float* __restrict__ inp, float* __restrict__ out)
{
    int idx = blockIdx.x * 256 + threadIdx.x;
    int c, b, chunk, dir;
    decode_idx(idx, c, b, chunk, dir);

    const int colg = dir ? (HALF + c) : c;
    const int colx = D_DIM + colg;
    const int colh = 2 * D_DIM + colg;
    const int t0 = chunk * CHUNK;

    float h = g_hin[((dir * NCHUNK + chunk) * B_DIM + b) * HALF + c];

    if (dir == 0) {
        for (int i = 0; i < CHUNK; i++) {
            size_t base = (size_t)((t0 + i) * B_DIM + b) * N3D;
            float g = g_pre[base + colg];
            float x = g_pre[base + colx];
            h = (1.f - g) * h + g * x;
            float hg = g_pre[base + colh];
            size_t ib = (size_t)((t0 + i) * B_DIM + b) * D_DIM + colg;
            out[ib] = h + hg * (inp[ib] - h);
        }
    } else {
        for (int i = CHUNK - 1; i >= 0; i--) {
            size_t base = (size_t)((t0 + i) * B_DIM + b) * N3D;
            float g = g_pre[base + colg];
            float x = g_pre[base + colx];
            h = (1.f - g) * h + g * x;
            float hg = g_pre[base + colh];
            size_t ib = (size_t)((t0 + i) * B_DIM + b) * D_DIM + colg;
            out[ib] = h + hg * (inp[ib] - h);
        }
    }
}

// =============================================================================
extern "C" void kernel_launch(void* const* d_in, const int* in_sizes, int n_in,
                              void* d_out, int out_size)
{
    const float* inp   = (const float*)d_in[0];   // (T,B,D)
    const float* W     = (const float*)d_in[1];   // (D, 3D)
    const float* gamma = (const float*)d_in[2];   // (3D,)
    const float* beta  = (const float*)d_in[3];   // (3D,)
    float* out = (float*)d_out;

    static bool attr_set = false;
    if (!attr_set) {
        cudaFuncSetAttribute(gemm_tf32_kernel,
                             cudaFuncAttributeMaxDynamicSharedMemorySize, SMEM_BYTES);
        attr_set = true;
    }

    dim3 ggrid(N3D / BN, MROWS / BM);             // 24 x 256
    gemm_tf32_kernel<<<ggrid, 256, SMEM_BYTES>>>(inp, W);

    ln_kernel<<<MROWS, 256>>>(gamma, beta);

    scan_passA_kernel<<<(2 * NCHUNK * B_DIM * HALF) / 256, 256>>>();
    scan_passB_kernel<<<(2 * B_DIM * HALF) / 256, 256>>>();
    scan_passC_kernel<<<(2 * NCHUNK * B_DIM * HALF) / 256, 256>>>(inp, out);
}